// round 12
// baseline (speedup 1.0000x reference)
#include <cuda_runtime.h>
#include <cuda_bf16.h>
#include <math.h>
#include <limits.h>

// FasterRCnn ROI target assignment: bucketed proposals (replicated counters)
// + atomic-free gt footprint lists at 40px cells.
//
// Correctness: outputs are zeros whenever max_iou < 0.5, so the argmax only
// needs to be exact over gts that can overlap the proposal. A gt can overlap
// a proposal iff the proposal CENTER lies in [g.x1-80, g.x2+80] x
// [g.y1-80, g.y2+80] (proposal half-size <= 80). Each gt is listed in every
// 40px cell its padded box touches (ascending gt order, deterministic); a
// proposal scans exactly its center cell's list. Surrogate score
// inter/(areaA+areaB) is strictly monotone in IoU; gt index packed into the
// low 8 mantissa bits preserves first-occurrence tie-break and makes the
// argmax order-independent (commutative int max), so bucket/fragment-order
// nondeterminism cannot change d_out. Exact IoU (both clamps, div.rn) is
// recomputed once per proposal for the 0.5 threshold.

constexpr int   NGT     = 256;
constexpr int   GRIDW   = 20;              // 40px cells
constexpr int   NCELL   = GRIDW * GRIDW;   // 400
constexpr float CELL_INV = 1.0f / 40.0f;
constexpr int   GT_FLAT = NGT * 81;        // footprint <= 9x9 cells per gt

constexpr int NREP   = 4;      // counter/slot replicas per cell (chain / 4)
constexpr int CAPR   = 320;    // slots per (cell, replica); mean ~164
constexpr int CHUNK  = 256;    // proposals per k_main block
constexpr int CHUNKS = 5;      // covers up to NREP*CAPR = 1280
constexpr int TPB_M  = 128;

constexpr int FILL_TPB = 256;
constexpr int FILL_PPT = 4;    // 1024 proposals/block -> 256 blocks

__device__ int           g_slots[NCELL * NREP * CAPR];
__device__ int           g_cnt[NCELL * NREP];   // zeroed by k_reset
__device__ unsigned char g_gtitems[GT_FLAT];
__device__ int           g_gtstart[NCELL + 1];

__device__ __forceinline__ int cell_of(float cx, float cy) {
    int xi = min(GRIDW - 1, max(0, (int)(cx * CELL_INV)));
    int yi = min(GRIDW - 1, max(0, (int)(cy * CELL_INV)));
    return yi * GRIDW + xi;
}

__device__ __forceinline__ void gt_footprint(const float4 g,
                                             int& x0, int& x1, int& y0, int& y1) {
    x0 = max(0,         (int)((g.x - 80.0f) * CELL_INV));
    x1 = min(GRIDW - 1, (int)((g.z + 80.0f) * CELL_INV));
    y0 = max(0,         (int)((g.y - 80.0f) * CELL_INV));
    y1 = min(GRIDW - 1, (int)((g.w + 80.0f) * CELL_INV));
}

// ---- pass 1: bucket proposals; extra block builds gt lists (no atomics) ----
__global__ __launch_bounds__(FILL_TPB)
void k_fill(const float4* __restrict__ props,
            const float4* __restrict__ gts, int NB)
{
    __shared__ int scnt[NCELL];
    __shared__ int sbase[NCELL];
    const int t = threadIdx.x;

    if (blockIdx.x == NB) {
        // ---- gt footprint lists: thread-per-cell containment, no atomics ----
        __shared__ float4 sg[NGT];
        sg[t] = gts[t];
        __syncthreads();
        // counts: cells t and t+256
        for (int cc = t; cc < NCELL; cc += FILL_TPB) {
            const int ccx = cc % GRIDW, ccy = cc / GRIDW;
            int cnt = 0;
            for (int j = 0; j < NGT; ++j) {
                int x0, x1, y0, y1; gt_footprint(sg[j], x0, x1, y0, y1);
                cnt += (ccx >= x0 && ccx <= x1 && ccy >= y0 && ccy <= y1);
            }
            scnt[cc] = cnt;
        }
        __syncthreads();
        // prefix (strided, O(NCELL) per thread — hidden behind fill blocks)
        for (int k = t; k <= NCELL; k += FILL_TPB) {
            int acc = 0;
            for (int q = 0; q < k && q < NCELL; ++q) acc += scnt[q];
            if (k < NCELL) sbase[k] = acc;
            g_gtstart[k] = acc;
        }
        __syncthreads();
        // append in ascending j (deterministic)
        for (int cc = t; cc < NCELL; cc += FILL_TPB) {
            const int ccx = cc % GRIDW, ccy = cc / GRIDW;
            int n = sbase[cc];
            for (int j = 0; j < NGT; ++j) {
                int x0, x1, y0, y1; gt_footprint(sg[j], x0, x1, y0, y1);
                if (ccx >= x0 && ccx <= x1 && ccy >= y0 && ccy <= y1)
                    g_gtitems[n++] = (unsigned char)j;
            }
        }
        return;
    }

    // ---- proposal bucketing: 4 proposals/thread, replica = blockIdx & 3 ----
    const int rep = blockIdx.x & (NREP - 1);
    for (int k = t; k < NCELL; k += FILL_TPB) scnt[k] = 0;
    __syncthreads();

    const int ibase = blockIdx.x * (FILL_TPB * FILL_PPT) + t;
    int c[FILL_PPT], r[FILL_PPT];
#pragma unroll
    for (int k = 0; k < FILL_PPT; ++k) {
        const float4 p = props[ibase + k * FILL_TPB];
        c[k] = cell_of(0.5f * (p.x + p.z), 0.5f * (p.y + p.w));
    }
#pragma unroll
    for (int k = 0; k < FILL_PPT; ++k)
        r[k] = atomicAdd(&scnt[c[k]], 1);
    __syncthreads();
    for (int k = t; k < NCELL; k += FILL_TPB)
        if (scnt[k]) sbase[k] = atomicAdd(&g_cnt[k * NREP + rep], scnt[k]);
    __syncthreads();
#pragma unroll
    for (int k = 0; k < FILL_PPT; ++k) {
        const int pos = sbase[c[k]] + r[k];
        if (pos < CAPR)
            g_slots[(c[k] * NREP + rep) * CAPR + pos] = ibase + k * FILL_TPB;
    }
}

// ---- finalize: exact IoU threshold + label/delta write ----
__device__ __forceinline__ void finalize(
    const float4* __restrict__ gts, const int* __restrict__ labels,
    float* __restrict__ out, int N, int i, float4 p, float pw, float ph,
    float areaA, int best)
{
    const int j = 255 - (best & 255);
    const float4 g = gts[j];

    const float lx = fmaxf(p.x, g.x), ly = fmaxf(p.y, g.y);
    const float rx = fminf(p.z, g.z), ry = fminf(p.w, g.w);
    const float w  = fmaxf(rx - lx, 0.0f);
    const float h  = fmaxf(ry - ly, 0.0f);
    const float inter = w * h;
    const float areaB = (g.z - g.x) * (g.w - g.y);
    const float uni   = areaA + areaB - inter;
    const float iou   = inter / uni;             // div.rn, matches reference
    const bool  pos   = (iou >= 0.5f);

    float lbl = 0.0f;
    float4 d  = make_float4(0.0f, 0.0f, 0.0f, 0.0f);
    if (pos) {
        const float gw = g.z - g.x;
        const float gh = g.w - g.y;
        const float px = p.x + 0.5f * pw;
        const float py = p.y + 0.5f * ph;
        const float gx = g.x + 0.5f * gw;
        const float gy = g.y + 0.5f * gh;
        d.x = (gx - px) / pw;
        d.y = (gy - py) / ph;
        d.z = logf(gw / pw);
        d.w = logf(gh / ph);
        lbl = (float)labels[j];
    }
    out[i] = lbl;
    reinterpret_cast<float4*>(out + N)[i] = d;
}

// map linear slot index s (< f[4] total) to fragment slot address
__device__ __forceinline__ int frag_addr(int cell, int s,
                                         int f1, int f2, int f3) {
    int r, off;
    if (s < f2) { r = (s < f1) ? 0 : 1; off = (s < f1) ? s : s - f1; }
    else        { r = (s < f3) ? 2 : 3; off = (s < f3) ? s - f2 : s - f3; }
    return (cell * NREP + r) * CAPR + off;
}

// ---- main: per-cell candidate scan, uniform trips, LDS broadcast ----
__global__ __launch_bounds__(TPB_M)
void k_main(const float4* __restrict__ props,
            const float4* __restrict__ gts,
            const int*    __restrict__ labels,
            float*        __restrict__ out,
            int N)
{
    __shared__ float4 sbox[NGT];
    __shared__ float2 smisc[NGT];   // (areaB, j as int bits)

    const int cell  = blockIdx.x / CHUNKS;
    const int chunk = blockIdx.x - cell * CHUNKS;

    const int4 c4 = *reinterpret_cast<const int4*>(&g_cnt[cell * NREP]);
    const int f1 = min(c4.x, CAPR);
    const int f2 = f1 + min(c4.y, CAPR);
    const int f3 = f2 + min(c4.z, CAPR);
    const int count = f3 + min(c4.w, CAPR);

    const int base = chunk * CHUNK;
    if (base >= count) return;

    const int t = threadIdx.x;

    const int s0 = min(base + t, count - 1);
    const int s1 = min(base + TPB_M + t, count - 1);
    const bool act0 = (base + t) < count;
    const bool act1 = (base + TPB_M + t) < count;
    const int i0 = g_slots[frag_addr(cell, s0, f1, f2, f3)];
    const int i1 = g_slots[frag_addr(cell, s1, f1, f2, f3)];
    const float4 p0 = props[i0];
    const float4 p1 = props[i1];

    const int kbeg = g_gtstart[cell];
    const int glen = g_gtstart[cell + 1] - kbeg;
    for (int k = t; k < glen; k += TPB_M) {
        const int j = g_gtitems[kbeg + k];
        const float4 g = gts[j];
        sbox[k]  = g;
        smisc[k] = make_float2((g.z - g.x) * (g.w - g.y), __int_as_float(j));
    }
    __syncthreads();

    const float pw0 = p0.z - p0.x, ph0 = p0.w - p0.y, aA0 = pw0 * ph0;
    const float pw1 = p1.z - p1.x, ph1 = p1.w - p1.y, aA1 = pw1 * ph1;

    int best0 = INT_MIN;
    int best1 = INT_MIN;

#pragma unroll 4
    for (int k = 0; k < glen; ++k) {
        const float4 gb = sbox[k];
        const float2 ms = smisc[k];
        const float  aB = ms.x;
        const int    j  = __float_as_int(ms.y);
        {
            const float lx = fmaxf(p0.x, gb.x);
            const float ly = fmaxf(p0.y, gb.y);
            const float rx = fminf(p0.z, gb.z);
            const float ry = fminf(p0.w, gb.w);
            const float w  = fmaxf(rx - lx, 0.0f);
            const float h  = ry - ly;              // unclamped: neg => score<=0
            const float inter = w * h;
            const float score = __fdividef(inter, aA0 + aB);
            const int packed  = (__float_as_int(score) | 255) - j;
            best0 = max(best0, packed);
        }
        {
            const float lx = fmaxf(p1.x, gb.x);
            const float ly = fmaxf(p1.y, gb.y);
            const float rx = fminf(p1.z, gb.z);
            const float ry = fminf(p1.w, gb.w);
            const float w  = fmaxf(rx - lx, 0.0f);
            const float h  = ry - ly;
            const float inter = w * h;
            const float score = __fdividef(inter, aA1 + aB);
            const int packed  = (__float_as_int(score) | 255) - j;
            best1 = max(best1, packed);
        }
    }

    if (act0) finalize(gts, labels, out, N, i0, p0, pw0, ph0, aA0, best0);
    if (act1) finalize(gts, labels, out, N, i1, p1, pw1, ph1, aA1, best1);
}

// ---- restore zero state for next graph replay ----
__global__ __launch_bounds__(512)
void k_reset() {
    const int t = threadIdx.x;
    for (int k = t; k < NCELL * NREP; k += 512) g_cnt[k] = 0;
}

extern "C" void kernel_launch(void* const* d_in, const int* in_sizes, int n_in,
                              void* d_out, int out_size)
{
    const float4* props  = (const float4*)d_in[0];
    const float4* gts    = (const float4*)d_in[1];
    const int*    labels = (const int*)d_in[2];
    float*        out    = (float*)d_out;

    const int N  = in_sizes[0] / 4;                // 262144
    const int NB = N / (FILL_TPB * FILL_PPT);      // 256 proposal blocks

    k_fill <<<NB + 1, FILL_TPB>>>(props, gts, NB);
    k_main <<<NCELL * CHUNKS, TPB_M>>>(props, gts, labels, out, N);
    k_reset<<<1, 512>>>();
}

// round 13
// speedup vs baseline: 3.1001x; 3.1001x over previous
#include <cuda_runtime.h>
#include <cuda_bf16.h>
#include <math.h>
#include <limits.h>

// FasterRCnn ROI target assignment: bucketed proposals (replicated counters),
// candidate gt lists built inline in k_main (no prep structure).
//
// Correctness: outputs are zeros whenever max_iou < 0.5, so the argmax only
// needs to be exact over gts that can overlap the proposal. A gt can overlap
// a proposal iff the proposal CENTER lies in [g.x1-80, g.x2+80] x
// [g.y1-80, g.y2+80] (proposal half-size <= 80, wh in [8,160]). Each k_main
// block serves one 40px cell and tests all 256 gts for footprint containment
// in its prologue. Surrogate score inter/(areaA+areaB) is strictly monotone
// in IoU; gt index packed into the low 8 mantissa bits preserves
// first-occurrence tie-break and makes the argmax order-independent
// (commutative int max), so bucket/compaction-order nondeterminism cannot
// change d_out. Exact IoU (both clamps, div.rn) is recomputed once per
// proposal for the 0.5 threshold.

constexpr int   NGT     = 256;
constexpr int   GRIDW   = 20;              // 40px cells
constexpr int   NCELL   = GRIDW * GRIDW;   // 400
constexpr float CELL_INV = 1.0f / 40.0f;

constexpr int NREP   = 4;      // counter/slot replicas per cell
constexpr int CAPR   = 320;    // slots per (cell, replica); mean ~164 (+10sd)
constexpr int CHUNK  = 256;    // proposals per k_main block
constexpr int CHUNKS = 4;      // covers 1024 >= max cell load (~770)
constexpr int TPB_M  = 128;

constexpr int FILL_TPB = 256;
constexpr int FILL_PPT = 4;    // 1024 proposals/block -> 256 blocks

__device__ int g_slots[NCELL * NREP * CAPR];
__device__ int g_cnt[NCELL * NREP];   // zeroed by k_reset each replay

__device__ __forceinline__ int cell_of(float cx, float cy) {
    int xi = min(GRIDW - 1, max(0, (int)(cx * CELL_INV)));
    int yi = min(GRIDW - 1, max(0, (int)(cy * CELL_INV)));
    return yi * GRIDW + xi;
}

// ---- pass 1: pure proposal bucketing, uniform grid ----
__global__ __launch_bounds__(FILL_TPB)
void k_fill(const float4* __restrict__ props)
{
    __shared__ int scnt[NCELL];
    __shared__ int sbase[NCELL];
    const int t   = threadIdx.x;
    const int rep = blockIdx.x & (NREP - 1);

    for (int k = t; k < NCELL; k += FILL_TPB) scnt[k] = 0;
    __syncthreads();

    const int ibase = blockIdx.x * (FILL_TPB * FILL_PPT) + t;
    int c[FILL_PPT], r[FILL_PPT];
#pragma unroll
    for (int k = 0; k < FILL_PPT; ++k) {
        const float4 p = props[ibase + k * FILL_TPB];
        c[k] = cell_of(0.5f * (p.x + p.z), 0.5f * (p.y + p.w));
    }
#pragma unroll
    for (int k = 0; k < FILL_PPT; ++k)
        r[k] = atomicAdd(&scnt[c[k]], 1);
    __syncthreads();
    for (int k = t; k < NCELL; k += FILL_TPB)
        if (scnt[k]) sbase[k] = atomicAdd(&g_cnt[k * NREP + rep], scnt[k]);
    __syncthreads();
#pragma unroll
    for (int k = 0; k < FILL_PPT; ++k) {
        const int pos = sbase[c[k]] + r[k];
        if (pos < CAPR)
            g_slots[(c[k] * NREP + rep) * CAPR + pos] = ibase + k * FILL_TPB;
    }
}

// ---- finalize: exact IoU threshold + label/delta write ----
__device__ __forceinline__ void finalize(
    const float4* __restrict__ gts, const int* __restrict__ labels,
    float* __restrict__ out, int N, int i, float4 p, float pw, float ph,
    float areaA, int best)
{
    const int j = 255 - (best & 255);
    const float4 g = gts[j];

    const float lx = fmaxf(p.x, g.x), ly = fmaxf(p.y, g.y);
    const float rx = fminf(p.z, g.z), ry = fminf(p.w, g.w);
    const float w  = fmaxf(rx - lx, 0.0f);
    const float h  = fmaxf(ry - ly, 0.0f);
    const float inter = w * h;
    const float areaB = (g.z - g.x) * (g.w - g.y);
    const float uni   = areaA + areaB - inter;
    const float iou   = inter / uni;             // div.rn, matches reference
    const bool  pos   = (iou >= 0.5f);

    float lbl = 0.0f;
    float4 d  = make_float4(0.0f, 0.0f, 0.0f, 0.0f);
    if (pos) {
        const float gw = g.z - g.x;
        const float gh = g.w - g.y;
        const float px = p.x + 0.5f * pw;
        const float py = p.y + 0.5f * ph;
        const float gx = g.x + 0.5f * gw;
        const float gy = g.y + 0.5f * gh;
        d.x = (gx - px) / pw;
        d.y = (gy - py) / ph;
        d.z = logf(gw / pw);
        d.w = logf(gh / ph);
        lbl = (float)labels[j];
    }
    out[i] = lbl;
    reinterpret_cast<float4*>(out + N)[i] = d;
}

// map linear slot index s to fragment slot address
__device__ __forceinline__ int frag_addr(int cell, int s,
                                         int f1, int f2, int f3) {
    int r, off;
    if (s < f2) { r = (s < f1) ? 0 : 1; off = (s < f1) ? s : s - f1; }
    else        { r = (s < f3) ? 2 : 3; off = (s < f3) ? s - f2 : s - f3; }
    return (cell * NREP + r) * CAPR + off;
}

// ---- main: inline candidate build + per-cell scan ----
__global__ __launch_bounds__(TPB_M)
void k_main(const float4* __restrict__ props,
            const float4* __restrict__ gts,
            const int*    __restrict__ labels,
            float*        __restrict__ out,
            int N)
{
    __shared__ float4 sbox[NGT];
    __shared__ float2 smisc[NGT];   // (areaB, j as int bits)
    __shared__ int    sncand;

    const int cell  = blockIdx.x >> 2;          // CHUNKS = 4
    const int chunk = blockIdx.x & (CHUNKS - 1);

    const int4 c4 = *reinterpret_cast<const int4*>(&g_cnt[cell * NREP]);
    const int f1 = min(c4.x, CAPR);
    const int f2 = f1 + min(c4.y, CAPR);
    const int f3 = f2 + min(c4.z, CAPR);
    const int count = f3 + min(c4.w, CAPR);

    const int base = chunk * CHUNK;
    if (base >= count) return;

    const int t = threadIdx.x;
    if (t == 0) sncand = 0;

    // long-latency proposal gathers first
    const int s0 = min(base + t, count - 1);
    const int s1 = min(base + TPB_M + t, count - 1);
    const bool act0 = (base + t) < count;
    const bool act1 = (base + TPB_M + t) < count;
    const int i0 = g_slots[frag_addr(cell, s0, f1, f2, f3)];
    const int i1 = g_slots[frag_addr(cell, s1, f1, f2, f3)];
    const float4 p0 = props[i0];
    const float4 p1 = props[i1];

    // inline candidate-list build: does this cell intersect gt j's padded box?
    const float cx0 = (cell % GRIDW) * 40.0f;
    const float cy0 = (cell / GRIDW) * 40.0f;
    __syncthreads();     // sncand = 0 visible
#pragma unroll
    for (int jj = 0; jj < 2; ++jj) {
        const int j = t + jj * TPB_M;
        const float4 g = gts[j];
        // padded box [g.x-80, g.z+80] x [g.y-80, g.w+80] vs cell [cx0,cx0+40]x[cy0,cy0+40]
        const bool hit = (g.z + 80.0f >= cx0) && (g.x - 80.0f < cx0 + 40.0f) &&
                         (g.w + 80.0f >= cy0) && (g.y - 80.0f < cy0 + 40.0f);
        if (hit) {
            const int k = atomicAdd(&sncand, 1);
            sbox[k]  = g;
            smisc[k] = make_float2((g.z - g.x) * (g.w - g.y), __int_as_float(j));
        }
    }
    __syncthreads();
    const int glen = sncand;

    const float pw0 = p0.z - p0.x, ph0 = p0.w - p0.y, aA0 = pw0 * ph0;
    const float pw1 = p1.z - p1.x, ph1 = p1.w - p1.y, aA1 = pw1 * ph1;

    int best0 = INT_MIN;
    int best1 = INT_MIN;

#pragma unroll 4
    for (int k = 0; k < glen; ++k) {
        const float4 gb = sbox[k];
        const float2 ms = smisc[k];
        const float  aB = ms.x;
        const int    j  = __float_as_int(ms.y);
        {
            const float lx = fmaxf(p0.x, gb.x);
            const float ly = fmaxf(p0.y, gb.y);
            const float rx = fminf(p0.z, gb.z);
            const float ry = fminf(p0.w, gb.w);
            const float w  = fmaxf(rx - lx, 0.0f);
            const float h  = ry - ly;              // unclamped: neg => score<=0
            const float inter = w * h;
            const float score = __fdividef(inter, aA0 + aB);
            const int packed  = (__float_as_int(score) | 255) - j;
            best0 = max(best0, packed);
        }
        {
            const float lx = fmaxf(p1.x, gb.x);
            const float ly = fmaxf(p1.y, gb.y);
            const float rx = fminf(p1.z, gb.z);
            const float ry = fminf(p1.w, gb.w);
            const float w  = fmaxf(rx - lx, 0.0f);
            const float h  = ry - ly;
            const float inter = w * h;
            const float score = __fdividef(inter, aA1 + aB);
            const int packed  = (__float_as_int(score) | 255) - j;
            best1 = max(best1, packed);
        }
    }

    if (act0) finalize(gts, labels, out, N, i0, p0, pw0, ph0, aA0, best0);
    if (act1) finalize(gts, labels, out, N, i1, p1, pw1, ph1, aA1, best1);
}

// ---- restore zero state for next graph replay ----
__global__ __launch_bounds__(512)
void k_reset() {
    const int t = threadIdx.x;
    for (int k = t; k < NCELL * NREP; k += 512) g_cnt[k] = 0;
}

extern "C" void kernel_launch(void* const* d_in, const int* in_sizes, int n_in,
                              void* d_out, int out_size)
{
    const float4* props  = (const float4*)d_in[0];
    const float4* gts    = (const float4*)d_in[1];
    const int*    labels = (const int*)d_in[2];
    float*        out    = (float*)d_out;

    const int N  = in_sizes[0] / 4;                // 262144
    const int NB = N / (FILL_TPB * FILL_PPT);      // 256 blocks

    k_fill <<<NB, FILL_TPB>>>(props);
    k_main <<<NCELL * CHUNKS, TPB_M>>>(props, gts, labels, out, N);
    k_reset<<<1, 512>>>();
}

// round 14
// speedup vs baseline: 3.2747x; 1.0563x over previous
#include <cuda_runtime.h>
#include <cuda_bf16.h>
#include <math.h>
#include <limits.h>

// FasterRCnn ROI target assignment: per-block private bucketing (no global
// atomics, no reset) + inline candidate gt lists in k_main.
//
// Correctness: outputs are zeros whenever max_iou < 0.5, so the argmax only
// needs to be exact over gts that can overlap the proposal. A gt can overlap
// a proposal iff the proposal CENTER lies in [g.x1-80, g.x2+80] x
// [g.y1-80, g.y2+80] (proposal half-size <= 80, wh in [8,160]). Each k_main
// block serves one 40px cell; its prologue tests all 256 gts for footprint
// intersection with the cell. Surrogate score inter/(areaA+areaB) is strictly
// monotone in IoU; gt index packed into the low 8 mantissa bits preserves
// first-occurrence tie-break and makes the argmax order-independent
// (commutative int max), so fragment/compaction-order nondeterminism cannot
// change d_out. Exact IoU (both clamps, div.rn) is recomputed once per
// proposal for the 0.5 threshold.
//
// State: g_cnt2 is fully overwritten by k_fill every run (all 400 counts per
// block, zeros included) and g_slots2 is only read below the written counts,
// so replays are deterministic with NO reset kernel.

constexpr int   NGT     = 256;
constexpr int   GRIDW   = 20;              // 40px cells
constexpr int   NCELL   = GRIDW * GRIDW;   // 400
constexpr float CELL_INV = 1.0f / 40.0f;

constexpr int NBLK   = 512;   // fill blocks = fragments per cell
constexpr int CAPB   = 16;    // slots per (cell, block); mean 1.28, P(ovf)~e^-28
constexpr int CHUNK  = 256;   // proposals per k_main block
constexpr int CHUNKS = 4;     // covers 1024 >= max cell load (~770)
constexpr int TPB_M  = 128;

constexpr int FILL_TPB = 256;
constexpr int FILL_PPT = 2;   // 512 proposals/block -> 512 blocks

__device__ int           g_slots2[NCELL * NBLK * CAPB];  // ~13 MB
__device__ unsigned char g_cnt2[NCELL * NBLK];           // [cell][block]

__device__ __forceinline__ int cell_of(float cx, float cy) {
    int xi = min(GRIDW - 1, max(0, (int)(cx * CELL_INV)));
    int yi = min(GRIDW - 1, max(0, (int)(cy * CELL_INV)));
    return yi * GRIDW + xi;
}

// ---- pass 1: private-fragment bucketing (smem atomics only) ----
__global__ __launch_bounds__(FILL_TPB)
void k_fill(const float4* __restrict__ props)
{
    __shared__ int scnt[NCELL];
    const int t = threadIdx.x;
    const int b = blockIdx.x;

    for (int k = t; k < NCELL; k += FILL_TPB) scnt[k] = 0;
    __syncthreads();

    const int ibase = b * (FILL_TPB * FILL_PPT) + t;
    int c[FILL_PPT], r[FILL_PPT];
#pragma unroll
    for (int k = 0; k < FILL_PPT; ++k) {
        const float4 p = props[ibase + k * FILL_TPB];
        c[k] = cell_of(0.5f * (p.x + p.z), 0.5f * (p.y + p.w));
    }
#pragma unroll
    for (int k = 0; k < FILL_PPT; ++k)
        r[k] = atomicAdd(&scnt[c[k]], 1);

    // slots can go out immediately (rank already owned)
#pragma unroll
    for (int k = 0; k < FILL_PPT; ++k)
        if (r[k] < CAPB)
            g_slots2[(c[k] * NBLK + b) * CAPB + r[k]] = ibase + k * FILL_TPB;

    __syncthreads();
    // write the FULL count row for this block (zeros included -> no reset)
    for (int k = t; k < NCELL; k += FILL_TPB)
        g_cnt2[k * NBLK + b] = (unsigned char)min(scnt[k], CAPB);
}

// ---- finalize: exact IoU threshold + label/delta write ----
__device__ __forceinline__ void finalize(
    const float4* __restrict__ gts, const int* __restrict__ labels,
    float* __restrict__ out, int N, int i, float4 p, float pw, float ph,
    float areaA, int best)
{
    const int j = 255 - (best & 255);
    const float4 g = gts[j];

    const float lx = fmaxf(p.x, g.x), ly = fmaxf(p.y, g.y);
    const float rx = fminf(p.z, g.z), ry = fminf(p.w, g.w);
    const float w  = fmaxf(rx - lx, 0.0f);
    const float h  = fmaxf(ry - ly, 0.0f);
    const float inter = w * h;
    const float areaB = (g.z - g.x) * (g.w - g.y);
    const float uni   = areaA + areaB - inter;
    const float iou   = inter / uni;             // div.rn, matches reference
    const bool  pos   = (iou >= 0.5f);

    float lbl = 0.0f;
    float4 d  = make_float4(0.0f, 0.0f, 0.0f, 0.0f);
    if (pos) {
        const float gw = g.z - g.x;
        const float gh = g.w - g.y;
        const float px = p.x + 0.5f * pw;
        const float py = p.y + 0.5f * ph;
        const float gx = g.x + 0.5f * gw;
        const float gy = g.y + 0.5f * gh;
        d.x = (gx - px) / pw;
        d.y = (gy - py) / ph;
        d.z = logf(gw / pw);
        d.w = logf(gh / ph);
        lbl = (float)labels[j];
    }
    out[i] = lbl;
    reinterpret_cast<float4*>(out + N)[i] = d;
}

// binary search: find f with P[f] <= s < P[f+1] over P[0..NBLK]
__device__ __forceinline__ int find_frag(const int* __restrict__ P, int s) {
    int lo = 0, hi = NBLK;
#pragma unroll
    for (int step = 0; step < 9; ++step) {   // 2^9 = 512
        const int mid = (lo + hi) >> 1;
        if (P[mid] <= s) lo = mid; else hi = mid;
    }
    return lo;
}

// ---- main: count-row scan + inline candidate build + per-cell argmax ----
__global__ __launch_bounds__(TPB_M)
void k_main(const float4* __restrict__ props,
            const float4* __restrict__ gts,
            const int*    __restrict__ labels,
            float*        __restrict__ out,
            int N)
{
    __shared__ float4 sbox[NGT];
    __shared__ float2 smisc[NGT];          // (areaB, j as int bits)
    __shared__ int    sprefix[NBLK + 1];   // fragment prefix sums
    __shared__ int    swsum[4];
    __shared__ int    sncand;

    const int cell  = blockIdx.x >> 2;     // CHUNKS = 4
    const int chunk = blockIdx.x & (CHUNKS - 1);
    const int t     = threadIdx.x;
    const int lane  = t & 31, wid = t >> 5;

    if (t == 0) sncand = 0;

    // ---- scan the 512-byte count row into a 513-entry prefix ----
    const unsigned int w4 =
        reinterpret_cast<const unsigned int*>(g_cnt2 + cell * NBLK)[t];
    const int b0 = w4 & 255, b1 = (w4 >> 8) & 255,
              b2 = (w4 >> 16) & 255, b3 = w4 >> 24;
    const int s4 = b0 + b1 + b2 + b3;

    int inc = s4;
#pragma unroll
    for (int off = 1; off < 32; off <<= 1) {
        const int n = __shfl_up_sync(0xffffffffu, inc, off);
        if (lane >= off) inc += n;
    }
    if (lane == 31) swsum[wid] = inc;
    __syncthreads();
    int woff = 0;
#pragma unroll
    for (int q = 0; q < 4; ++q) woff += (q < wid) ? swsum[q] : 0;
    const int excl = woff + inc - s4;
    sprefix[4 * t + 0] = excl;
    sprefix[4 * t + 1] = excl + b0;
    sprefix[4 * t + 2] = excl + b0 + b1;
    sprefix[4 * t + 3] = excl + b0 + b1 + b2;
    if (t == TPB_M - 1) sprefix[NBLK] = excl + s4;
    __syncthreads();

    const int count = sprefix[NBLK];
    const int base  = chunk * CHUNK;
    if (base >= count) return;

    // ---- locate + gather proposals (long latency first) ----
    const int s0 = min(base + t, count - 1);
    const int s1 = min(base + TPB_M + t, count - 1);
    const bool act0 = (base + t) < count;
    const bool act1 = (base + TPB_M + t) < count;
    const int f0 = find_frag(sprefix, s0);
    const int f1 = find_frag(sprefix, s1);
    const int i0 = g_slots2[(cell * NBLK + f0) * CAPB + (s0 - sprefix[f0])];
    const int i1 = g_slots2[(cell * NBLK + f1) * CAPB + (s1 - sprefix[f1])];
    const float4 p0 = props[i0];
    const float4 p1 = props[i1];

    // ---- inline candidate build: cell vs padded gt boxes ----
    const float cx0 = (cell % GRIDW) * 40.0f;
    const float cy0 = (cell / GRIDW) * 40.0f;
#pragma unroll
    for (int jj = 0; jj < 2; ++jj) {
        const int j = t + jj * TPB_M;
        const float4 g = gts[j];
        const bool hit = (g.z + 80.0f >= cx0) && (g.x - 80.0f < cx0 + 40.0f) &&
                         (g.w + 80.0f >= cy0) && (g.y - 80.0f < cy0 + 40.0f);
        if (hit) {
            const int k = atomicAdd(&sncand, 1);
            sbox[k]  = g;
            smisc[k] = make_float2((g.z - g.x) * (g.w - g.y), __int_as_float(j));
        }
    }
    __syncthreads();
    const int glen = sncand;

    const float pw0 = p0.z - p0.x, ph0 = p0.w - p0.y, aA0 = pw0 * ph0;
    const float pw1 = p1.z - p1.x, ph1 = p1.w - p1.y, aA1 = pw1 * ph1;

    int best0 = INT_MIN;
    int best1 = INT_MIN;

#pragma unroll 4
    for (int k = 0; k < glen; ++k) {
        const float4 gb = sbox[k];
        const float2 ms = smisc[k];
        const float  aB = ms.x;
        const int    j  = __float_as_int(ms.y);
        {
            const float lx = fmaxf(p0.x, gb.x);
            const float ly = fmaxf(p0.y, gb.y);
            const float rx = fminf(p0.z, gb.z);
            const float ry = fminf(p0.w, gb.w);
            const float w  = fmaxf(rx - lx, 0.0f);
            const float h  = ry - ly;              // unclamped: neg => score<=0
            const float inter = w * h;
            const float score = __fdividef(inter, aA0 + aB);
            const int packed  = (__float_as_int(score) | 255) - j;
            best0 = max(best0, packed);
        }
        {
            const float lx = fmaxf(p1.x, gb.x);
            const float ly = fmaxf(p1.y, gb.y);
            const float rx = fminf(p1.z, gb.z);
            const float ry = fminf(p1.w, gb.w);
            const float w  = fmaxf(rx - lx, 0.0f);
            const float h  = ry - ly;
            const float inter = w * h;
            const float score = __fdividef(inter, aA1 + aB);
            const int packed  = (__float_as_int(score) | 255) - j;
            best1 = max(best1, packed);
        }
    }

    if (act0) finalize(gts, labels, out, N, i0, p0, pw0, ph0, aA0, best0);
    if (act1) finalize(gts, labels, out, N, i1, p1, pw1, ph1, aA1, best1);
}

extern "C" void kernel_launch(void* const* d_in, const int* in_sizes, int n_in,
                              void* d_out, int out_size)
{
    const float4* props  = (const float4*)d_in[0];
    const float4* gts    = (const float4*)d_in[1];
    const int*    labels = (const int*)d_in[2];
    float*        out    = (float*)d_out;

    const int N = in_sizes[0] / 4;               // 262144

    k_fill<<<NBLK, FILL_TPB>>>(props);           // N / (256*2) = 512 blocks
    k_main<<<NCELL * CHUNKS, TPB_M>>>(props, gts, labels, out, N);
}

// round 15
// speedup vs baseline: 3.4155x; 1.0430x over previous
#include <cuda_runtime.h>
#include <cuda_bf16.h>
#include <math.h>
#include <limits.h>

// FasterRCnn ROI target assignment: per-block private bucketing (no global
// atomics, no reset) + fragment-aligned k_main chunks (no binary search).
//
// Correctness: outputs are zeros whenever max_iou < 0.5, so the argmax only
// needs to be exact over gts that can overlap the proposal. A gt can overlap
// a proposal iff the proposal CENTER lies in [g.x1-80, g.x2+80] x
// [g.y1-80, g.y2+80] (proposal half-size <= 80, wh in [8,160]). Each k_main
// block serves one 40px cell x 128-fragment range; its prologue tests all
// 256 gts for footprint intersection with the cell. Surrogate score
// inter/(areaA+areaB) is strictly monotone in IoU; gt index packed into the
// low 8 mantissa bits preserves first-occurrence tie-break and makes the
// argmax order-independent (commutative int max), so fragment/compaction
// order nondeterminism cannot change d_out. Exact IoU (both clamps, div.rn)
// is recomputed once per proposal for the 0.5 threshold.
//
// State: g_cnt2 is fully overwritten by k_fill every run (zeros included) and
// g_slots2 is only read below the written counts -> deterministic replays
// with no reset kernel.

constexpr int   NGT     = 256;
constexpr int   GRIDW   = 20;              // 40px cells
constexpr int   NCELL   = GRIDW * GRIDW;   // 400
constexpr float CELL_INV = 1.0f / 40.0f;

constexpr int NBLK   = 512;   // fill blocks = fragments per cell
constexpr int CAPB   = 16;    // slots per (cell, fragment); mean 1.28
constexpr int CHUNKS = 4;     // fragment ranges per cell
constexpr int FRAGS  = NBLK / CHUNKS;   // 128 fragments per k_main block
constexpr int TPB_M  = 128;
constexpr int QCAP   = 384;   // smem queue; block mean 164, sd ~13 (+17sd)

constexpr int FILL_TPB = 256;
constexpr int FILL_PPT = 2;   // 512 proposals/block -> 512 blocks

__device__ int           g_slots2[NCELL * NBLK * CAPB];
__device__ unsigned char g_cnt2[NCELL * NBLK];           // [cell][fragment]

__device__ __forceinline__ int cell_of(float cx, float cy) {
    int xi = min(GRIDW - 1, max(0, (int)(cx * CELL_INV)));
    int yi = min(GRIDW - 1, max(0, (int)(cy * CELL_INV)));
    return yi * GRIDW + xi;
}

// ---- pass 1: private-fragment bucketing (smem atomics only) ----
__global__ __launch_bounds__(FILL_TPB)
void k_fill(const float4* __restrict__ props)
{
    __shared__ int scnt[NCELL];
    const int t = threadIdx.x;
    const int b = blockIdx.x;

    for (int k = t; k < NCELL; k += FILL_TPB) scnt[k] = 0;
    __syncthreads();

    const int ibase = b * (FILL_TPB * FILL_PPT) + t;
    int c[FILL_PPT], r[FILL_PPT];
#pragma unroll
    for (int k = 0; k < FILL_PPT; ++k) {
        const float4 p = props[ibase + k * FILL_TPB];
        c[k] = cell_of(0.5f * (p.x + p.z), 0.5f * (p.y + p.w));
    }
#pragma unroll
    for (int k = 0; k < FILL_PPT; ++k)
        r[k] = atomicAdd(&scnt[c[k]], 1);

#pragma unroll
    for (int k = 0; k < FILL_PPT; ++k)
        if (r[k] < CAPB)
            g_slots2[(c[k] * NBLK + b) * CAPB + r[k]] = ibase + k * FILL_TPB;

    __syncthreads();
    for (int k = t; k < NCELL; k += FILL_TPB)
        g_cnt2[k * NBLK + b] = (unsigned char)min(scnt[k], CAPB);
}

// ---- finalize: exact IoU threshold + label/delta write ----
__device__ __forceinline__ void finalize(
    const float4* __restrict__ gts, const int* __restrict__ labels,
    float* __restrict__ out, int N, int i, float4 p, float pw, float ph,
    float areaA, int best)
{
    const int j = 255 - (best & 255);
    const float4 g = gts[j];

    const float lx = fmaxf(p.x, g.x), ly = fmaxf(p.y, g.y);
    const float rx = fminf(p.z, g.z), ry = fminf(p.w, g.w);
    const float w  = fmaxf(rx - lx, 0.0f);
    const float h  = fmaxf(ry - ly, 0.0f);
    const float inter = w * h;
    const float areaB = (g.z - g.x) * (g.w - g.y);
    const float uni   = areaA + areaB - inter;
    const float iou   = inter / uni;             // div.rn, matches reference
    const bool  pos   = (iou >= 0.5f);

    float lbl = 0.0f;
    float4 d  = make_float4(0.0f, 0.0f, 0.0f, 0.0f);
    if (pos) {
        const float gw = g.z - g.x;
        const float gh = g.w - g.y;
        const float px = p.x + 0.5f * pw;
        const float py = p.y + 0.5f * ph;
        const float gx = g.x + 0.5f * gw;
        const float gy = g.y + 0.5f * gh;
        d.x = (gx - px) / pw;
        d.y = (gy - py) / ph;
        d.z = logf(gw / pw);
        d.w = logf(gh / ph);
        lbl = (float)labels[j];
    }
    out[i] = lbl;
    reinterpret_cast<float4*>(out + N)[i] = d;
}

// ---- main: fragment-range compaction + inline candidates + argmax ----
__global__ __launch_bounds__(TPB_M)
void k_main(const float4* __restrict__ props,
            const float4* __restrict__ gts,
            const int*    __restrict__ labels,
            float*        __restrict__ out,
            int N)
{
    __shared__ float4 sbox[NGT];
    __shared__ float2 smisc[NGT];   // (areaB, j as int bits)
    __shared__ int    squeue[QCAP];
    __shared__ int    swsum[4];
    __shared__ int    sncand;

    const int cell  = blockIdx.x >> 2;          // CHUNKS = 4
    const int chunk = blockIdx.x & (CHUNKS - 1);
    const int t     = threadIdx.x;
    const int lane  = t & 31, wid = t >> 5;

    if (t == 0) sncand = 0;

    // ---- fragment counts for this range (coalesced 128-byte load) ----
    const int fragbase = cell * NBLK + chunk * FRAGS;
    const int cnt = g_cnt2[fragbase + t];

    // block scan of cnt -> exclusive offsets
    int inc = cnt;
#pragma unroll
    for (int off = 1; off < 32; off <<= 1) {
        const int n = __shfl_up_sync(0xffffffffu, inc, off);
        if (lane >= off) inc += n;
    }
    if (lane == 31) swsum[wid] = inc;
    __syncthreads();
    int woff = 0;
#pragma unroll
    for (int q = 0; q < 4; ++q) woff += (q < wid) ? swsum[q] : 0;
    const int excl  = woff + inc - cnt;
    const int count = min(swsum[0] + swsum[1] + swsum[2] + swsum[3], QCAP);

    // copy my fragment's slot ids into the queue (independent LDGs, high MLP)
    {
        const int sb = (fragbase + t) * CAPB;
        for (int q = 0; q < cnt; ++q) {
            const int pos = excl + q;
            if (pos < QCAP) squeue[pos] = g_slots2[sb + q];
        }
    }

    // ---- inline candidate build: cell vs padded gt boxes ----
    const float cx0 = (cell % GRIDW) * 40.0f;
    const float cy0 = (cell / GRIDW) * 40.0f;
#pragma unroll
    for (int jj = 0; jj < 2; ++jj) {
        const int j = t + jj * TPB_M;
        const float4 g = gts[j];
        const bool hit = (g.z + 80.0f >= cx0) && (g.x - 80.0f < cx0 + 40.0f) &&
                         (g.w + 80.0f >= cy0) && (g.y - 80.0f < cy0 + 40.0f);
        if (hit) {
            const int k = atomicAdd(&sncand, 1);
            sbox[k]  = g;
            smisc[k] = make_float2((g.z - g.x) * (g.w - g.y), __int_as_float(j));
        }
    }
    __syncthreads();
    const int glen = sncand;
    if (count == 0) return;

    // ---- gather proposals ----
    const bool act0 = t < count;
    const bool act1 = (TPB_M + t) < count;
    const int i0 = squeue[min(t, count - 1)];
    const int i1 = squeue[min(TPB_M + t, count - 1)];
    const float4 p0 = props[i0];
    const float4 p1 = props[i1];

    const float pw0 = p0.z - p0.x, ph0 = p0.w - p0.y, aA0 = pw0 * ph0;
    const float pw1 = p1.z - p1.x, ph1 = p1.w - p1.y, aA1 = pw1 * ph1;

    int best0 = INT_MIN;
    int best1 = INT_MIN;

#pragma unroll 4
    for (int k = 0; k < glen; ++k) {
        const float4 gb = sbox[k];
        const float2 ms = smisc[k];
        const float  aB = ms.x;
        const int    j  = __float_as_int(ms.y);
        {
            const float lx = fmaxf(p0.x, gb.x);
            const float ly = fmaxf(p0.y, gb.y);
            const float rx = fminf(p0.z, gb.z);
            const float ry = fminf(p0.w, gb.w);
            const float w  = fmaxf(rx - lx, 0.0f);
            const float h  = ry - ly;              // unclamped: neg => score<=0
            const float inter = w * h;
            const float score = __fdividef(inter, aA0 + aB);
            const int packed  = (__float_as_int(score) | 255) - j;
            best0 = max(best0, packed);
        }
        {
            const float lx = fmaxf(p1.x, gb.x);
            const float ly = fmaxf(p1.y, gb.y);
            const float rx = fminf(p1.z, gb.z);
            const float ry = fminf(p1.w, gb.w);
            const float w  = fmaxf(rx - lx, 0.0f);
            const float h  = ry - ly;
            const float inter = w * h;
            const float score = __fdividef(inter, aA1 + aB);
            const int packed  = (__float_as_int(score) | 255) - j;
            best1 = max(best1, packed);
        }
    }

    if (act0) finalize(gts, labels, out, N, i0, p0, pw0, ph0, aA0, best0);
    if (act1) finalize(gts, labels, out, N, i1, p1, pw1, ph1, aA1, best1);
}

extern "C" void kernel_launch(void* const* d_in, const int* in_sizes, int n_in,
                              void* d_out, int out_size)
{
    const float4* props  = (const float4*)d_in[0];
    const float4* gts    = (const float4*)d_in[1];
    const int*    labels = (const int*)d_in[2];
    float*        out    = (float*)d_out;

    const int N = in_sizes[0] / 4;               // 262144

    k_fill<<<NBLK, FILL_TPB>>>(props);           // 512 blocks
    k_main<<<NCELL * CHUNKS, TPB_M>>>(props, gts, labels, out, N);
}

// round 17
// speedup vs baseline: 3.6397x; 1.0656x over previous
#include <cuda_runtime.h>
#include <cuda_bf16.h>
#include <math.h>
#include <limits.h>

// FasterRCnn ROI target assignment: per-block private bucketing (no global
// atomics, no reset) + fragment-aligned k_main chunks + warp-specialized
// one/two-stream inner loops.
//
// Correctness: outputs are zeros whenever max_iou < 0.5, so the argmax only
// needs to be exact over gts that can overlap the proposal. A gt can overlap
// a proposal iff the proposal CENTER lies in [g.x1-80, g.x2+80] x
// [g.y1-80, g.y2+80] (proposal half-size <= 80, wh in [8,160]). Each k_main
// block serves one 40px cell x 128-fragment range; its prologue tests all
// 256 gts for footprint intersection with the cell. Surrogate score
// inter/(areaA+areaB) is strictly monotone in IoU; gt index packed into the
// low 8 mantissa bits preserves first-occurrence tie-break and makes the
// argmax order-independent (commutative int max), so fragment/compaction
// order nondeterminism cannot change d_out. Exact IoU (both clamps, div.rn)
// is recomputed once per proposal for the 0.5 threshold.
//
// State: g_cnt2 is fully overwritten by k_fill every run (zeros included) and
// g_slots2 is only read below the written counts -> deterministic replays
// with no reset kernel.

constexpr int   NGT     = 256;
constexpr int   GRIDW   = 20;              // 40px cells
constexpr int   NCELL   = GRIDW * GRIDW;   // 400
constexpr float CELL_INV = 1.0f / 40.0f;

constexpr int NBLK   = 512;   // fill blocks = fragments per cell
constexpr int CAPB   = 16;    // slots per (cell, fragment); mean 1.28
constexpr int CHUNKS = 4;     // fragment ranges per cell
constexpr int FRAGS  = NBLK / CHUNKS;   // 128 fragments per k_main block
constexpr int TPB_M  = 128;
constexpr int QCAP   = 384;   // smem queue; block mean 164, sd ~13 (+17sd)

constexpr int FILL_TPB = 256;
constexpr int FILL_PPT = 2;   // 512 proposals/block -> 512 blocks

__device__ int           g_slots2[NCELL * NBLK * CAPB];
__device__ unsigned char g_cnt2[NCELL * NBLK];           // [cell][fragment]

__device__ __forceinline__ int cell_of(float cx, float cy) {
    int xi = min(GRIDW - 1, max(0, (int)(cx * CELL_INV)));
    int yi = min(GRIDW - 1, max(0, (int)(cy * CELL_INV)));
    return yi * GRIDW + xi;
}

// ---- pass 1: private-fragment bucketing (smem atomics only) ----
__global__ __launch_bounds__(FILL_TPB)
void k_fill(const float4* __restrict__ props)
{
    __shared__ int scnt[NCELL];
    const int t = threadIdx.x;
    const int b = blockIdx.x;

    for (int k = t; k < NCELL; k += FILL_TPB) scnt[k] = 0;
    __syncthreads();

    const int ibase = b * (FILL_TPB * FILL_PPT) + t;
    int c[FILL_PPT], r[FILL_PPT];
#pragma unroll
    for (int k = 0; k < FILL_PPT; ++k) {
        const float4 p = props[ibase + k * FILL_TPB];
        c[k] = cell_of(0.5f * (p.x + p.z), 0.5f * (p.y + p.w));
    }
#pragma unroll
    for (int k = 0; k < FILL_PPT; ++k)
        r[k] = atomicAdd(&scnt[c[k]], 1);

#pragma unroll
    for (int k = 0; k < FILL_PPT; ++k)
        if (r[k] < CAPB)
            g_slots2[(c[k] * NBLK + b) * CAPB + r[k]] = ibase + k * FILL_TPB;

    __syncthreads();
    for (int k = t; k < NCELL; k += FILL_TPB)
        g_cnt2[k * NBLK + b] = (unsigned char)min(scnt[k], CAPB);
}

// ---- finalize: exact IoU threshold + label/delta write ----
__device__ __forceinline__ void finalize(
    const float4* __restrict__ gts, const int* __restrict__ labels,
    float* __restrict__ out, int N, int i, float4 p, float pw, float ph,
    float areaA, int best)
{
    const int j = 255 - (best & 255);
    const float4 g = gts[j];

    const float lx = fmaxf(p.x, g.x), ly = fmaxf(p.y, g.y);
    const float rx = fminf(p.z, g.z), ry = fminf(p.w, g.w);
    const float w  = fmaxf(rx - lx, 0.0f);
    const float h  = fmaxf(ry - ly, 0.0f);
    const float inter = w * h;
    const float areaB = (g.z - g.x) * (g.w - g.y);
    const float uni   = areaA + areaB - inter;
    const float iou   = inter / uni;             // div.rn, matches reference
    const bool  pos   = (iou >= 0.5f);

    float lbl = 0.0f;
    float4 d  = make_float4(0.0f, 0.0f, 0.0f, 0.0f);
    if (pos) {
        const float gw = g.z - g.x;
        const float gh = g.w - g.y;
        const float px = p.x + 0.5f * pw;
        const float py = p.y + 0.5f * ph;
        const float gx = g.x + 0.5f * gw;
        const float gy = g.y + 0.5f * gh;
        d.x = (gx - px) / pw;
        d.y = (gy - py) / ph;
        d.z = logf(gw / pw);
        d.w = logf(gh / ph);
        lbl = (float)labels[j];
    }
    out[i] = lbl;
    reinterpret_cast<float4*>(out + N)[i] = d;
}

// one proposal-gt surrogate score step
__device__ __forceinline__ void score_step(
    const float4 p, const float aA, const float4 gb, const float aB,
    const int j, int& best)
{
    const float lx = fmaxf(p.x, gb.x);
    const float ly = fmaxf(p.y, gb.y);
    const float rx = fminf(p.z, gb.z);
    const float ry = fminf(p.w, gb.w);
    const float w  = fmaxf(rx - lx, 0.0f);
    const float h  = ry - ly;                  // unclamped: neg => score<=0
    const float inter = w * h;
    const float score = __fdividef(inter, aA + aB);
    const int packed  = (__float_as_int(score) | 255) - j;
    best = max(best, packed);
}

// ---- main: fragment-range compaction + inline candidates + argmax ----
__global__ __launch_bounds__(TPB_M)
void k_main(const float4* __restrict__ props,
            const float4* __restrict__ gts,
            const int*    __restrict__ labels,
            float*        __restrict__ out,
            int N)
{
    __shared__ float4 sbox[NGT];
    __shared__ float2 smisc[NGT];   // (areaB, j as int bits)
    __shared__ int    squeue[QCAP];
    __shared__ int    swsum[4];
    __shared__ int    sncand;

    const int cell  = blockIdx.x >> 2;          // CHUNKS = 4
    const int chunk = blockIdx.x & (CHUNKS - 1);
    const int t     = threadIdx.x;
    const int lane  = t & 31, wid = t >> 5;

    if (t == 0) sncand = 0;

    // ---- fragment counts for this range (coalesced 128-byte load) ----
    const int fragbase = cell * NBLK + chunk * FRAGS;
    const int cnt = g_cnt2[fragbase + t];

    // block scan of cnt -> exclusive offsets
    int inc = cnt;
#pragma unroll
    for (int off = 1; off < 32; off <<= 1) {
        const int n = __shfl_up_sync(0xffffffffu, inc, off);
        if (lane >= off) inc += n;
    }
    if (lane == 31) swsum[wid] = inc;
    __syncthreads();
    int woff = 0;
#pragma unroll
    for (int q = 0; q < 4; ++q) woff += (q < wid) ? swsum[q] : 0;
    const int excl  = woff + inc - cnt;
    const int count = min(swsum[0] + swsum[1] + swsum[2] + swsum[3], QCAP);

    // copy my fragment's slot ids into the queue (independent LDGs, high MLP)
    {
        const int sb = (fragbase + t) * CAPB;
        for (int q = 0; q < cnt; ++q) {
            const int pos = excl + q;
            if (pos < QCAP) squeue[pos] = g_slots2[sb + q];
        }
    }

    // ---- inline candidate build: cell vs padded gt boxes ----
    const float cx0 = (cell % GRIDW) * 40.0f;
    const float cy0 = (cell / GRIDW) * 40.0f;
#pragma unroll
    for (int jj = 0; jj < 2; ++jj) {
        const int j = t + jj * TPB_M;
        const float4 g = gts[j];
        const bool hit = (g.z + 80.0f >= cx0) && (g.x - 80.0f < cx0 + 40.0f) &&
                         (g.w + 80.0f >= cy0) && (g.y - 80.0f < cy0 + 40.0f);
        if (hit) {
            const int k = atomicAdd(&sncand, 1);
            sbox[k]  = g;
            smisc[k] = make_float2((g.z - g.x) * (g.w - g.y), __int_as_float(j));
        }
    }
    __syncthreads();
    const int glen = sncand;
    if (count == 0) return;

    // ---- gather proposals ----
    const bool act0 = t < count;
    const bool act1 = (TPB_M + t) < count;
    const int i0 = squeue[min(t, count - 1)];
    const int i1 = squeue[min(TPB_M + t, count - 1)];
    const float4 p0 = props[i0];
    const float4 p1 = props[i1];

    const float pw0 = p0.z - p0.x, ph0 = p0.w - p0.y, aA0 = pw0 * ph0;
    const float pw1 = p1.z - p1.x, ph1 = p1.w - p1.y, aA1 = pw1 * ph1;

    int best0 = INT_MIN;
    int best1 = INT_MIN;

    // warp-specialized: warps with no active second proposal run a
    // single-stream loop (saves ~45% of inner-loop issue for those warps)
    const unsigned warp_has_s1 = __ballot_sync(0xffffffffu, act1);

    if (warp_has_s1) {
#pragma unroll 4
        for (int k = 0; k < glen; ++k) {
            const float4 gb = sbox[k];
            const float2 ms = smisc[k];
            const int    j  = __float_as_int(ms.y);
            score_step(p0, aA0, gb, ms.x, j, best0);
            score_step(p1, aA1, gb, ms.x, j, best1);
        }
    } else {
#pragma unroll 4
        for (int k = 0; k < glen; ++k) {
            const float4 gb = sbox[k];
            const float2 ms = smisc[k];
            const int    j  = __float_as_int(ms.y);
            score_step(p0, aA0, gb, ms.x, j, best0);
        }
    }

    if (act0) finalize(gts, labels, out, N, i0, p0, pw0, ph0, aA0, best0);
    if (act1) finalize(gts, labels, out, N, i1, p1, pw1, ph1, aA1, best1);
}

extern "C" void kernel_launch(void* const* d_in, const int* in_sizes, int n_in,
                              void* d_out, int out_size)
{
    const float4* props  = (const float4*)d_in[0];
    const float4* gts    = (const float4*)d_in[1];
    const int*    labels = (const int*)d_in[2];
    float*        out    = (float*)d_out;

    const int N = in_sizes[0] / 4;               // 262144

    k_fill<<<NBLK, FILL_TPB>>>(props);           // 512 blocks
    k_main<<<NCELL * CHUNKS, TPB_M>>>(props, gts, labels, out, N);
}